// round 4
// baseline (speedup 1.0000x reference)
#include <cuda_runtime.h>
#include <math.h>
#include <stdint.h>

#define H_IMG 200
#define W_IMG 200
#define HW    40000
#define C1    64
#define C3    256
#define NHEADS 8
#define HD    32
#define BSZ   2
#define CF    1024
#define ATT_SCALE 0.17677669529663687f   // 32^-0.5

// ---------------- static scratch ----------------
__device__ float g_Q  [BSZ * C3 * HW];   // NCHW
__device__ float g_K  [BSZ * C3 * HW];
__device__ float g_V  [BSZ * C3 * HW];
__device__ float g_AO [BSZ * HW * C3];   // NHWC, tf32-rounded
__device__ float g_X  [BSZ * HW * C3];   // NHWC
__device__ float g_Y  [BSZ * HW * C3];   // NHWC
__device__ float g_Hid[BSZ * HW * CF];   // tf32-rounded
__device__ float g_Fl [BSZ * C1 * HW];   // tf32-rounded F_lidar
__device__ float g_Fc [BSZ * C3 * HW];   // tf32-rounded F_cam
__device__ float g_Wb [753664];          // tf32-rounded weights

__device__ __forceinline__ float rna_tf32(float x) {
    uint32_t u;
    asm("cvt.rna.tf32.f32 %0, %1;" : "=r"(u) : "f"(x));
    return __uint_as_float(u);
}

// ---------------- tf32 rounding prep ----------------
__global__ __launch_bounds__(256) void round_k(
    const float4* __restrict__ s, float4* __restrict__ d, int n4)
{
    int i = blockIdx.x * 256 + threadIdx.x;
    if (i < n4) {
        float4 v = s[i];
        v.x = rna_tf32(v.x); v.y = rna_tf32(v.y);
        v.z = rna_tf32(v.z); v.w = rna_tf32(v.w);
        d[i] = v;
    }
}

// ---------------- cp.async helpers ----------------
__device__ __forceinline__ void cpa16(uint32_t s, const void* g, int ok) {
    asm volatile("cp.async.cg.shared.global [%0], [%1], 16, %2;\n"
                 :: "r"(s), "l"(g), "r"(ok ? 16 : 0));
}
__device__ __forceinline__ void cpa_commit() {
    asm volatile("cp.async.commit_group;\n");
}

// ---------------- tf32 tensor-core GEMM, cp.async 2-stage, BK=32 ----------------
// TA=0: A row-major [M,K]. TA=1: A stored [K,M].
// TB=0: B row-major [K,N]. TB=1: B stored [N,K] (B^T used).
// smem/stage: A 4608 f32 (18432B), B 4608 f32. 2 stages = 73728B dynamic.
template<int TA, int TB, int ACCU, int RELU, int BIAS, int ROUND>
__global__ __launch_bounds__(256, 2) void gemm_tc(
    const float* __restrict__ A, const float* __restrict__ B,
    const float* __restrict__ bias, float* __restrict__ C,
    int M, int N, int K, long aStr, long bStr, long cStr)
{
    extern __shared__ __align__(16) float smbuf[];
    A += (long)blockIdx.z * aStr;
    B += (long)blockIdx.z * bStr;
    C += (long)blockIdx.z * cStr;

    const int m0 = blockIdx.y * 128;
    const int n0 = blockIdx.x * 128;
    const int t    = threadIdx.x;
    const int lane = t & 31, w = t >> 5;
    const int g  = lane >> 2, tg = lane & 3;
    const int wmB = (w & 1) * 64, wnB = (w >> 1) * 32;

    const uint32_t sbase = (uint32_t)__cvta_generic_to_shared(smbuf);

    float acc[4][4][4];
#pragma unroll
    for (int i = 0; i < 4; i++)
#pragma unroll
        for (int j = 0; j < 4; j++)
#pragma unroll
            for (int r = 0; r < 4; r++) acc[i][j][r] = 0.f;

    auto issue_stage = [&](int kt, int s) {
        const uint32_t sA = sbase + s * 36864;
        const uint32_t sB = sA + 18432;
        const int k0 = kt * 32;
#pragma unroll
        for (int v = 0; v < 4; v++) {
            int idx = t + v * 256;
            if (TA == 0) {
                int m = idx >> 3, kc = (idx & 7) << 2;
                cpa16(sA + (m * 36 + kc) * 4,
                      A + (long)(m0 + m) * K + k0 + kc, 1);
            } else {
                int k = idx >> 5, mc = (idx & 31) << 2;
                int ok = (m0 + mc) < M;
                const float* p = ok ? (A + (long)(k0 + k) * M + m0 + mc) : A;
                cpa16(sA + (k * 136 + mc) * 4, p, ok);
            }
        }
#pragma unroll
        for (int v = 0; v < 4; v++) {
            int idx = t + v * 256;
            if (TB == 0) {
                int k = idx >> 5, nc = (idx & 31) << 2;
                int ok = (n0 + nc) < N;
                const float* p = ok ? (B + (long)(k0 + k) * N + n0 + nc) : B;
                cpa16(sB + (k * 136 + nc) * 4, p, ok);
            } else {
                int n = idx >> 3, kc = (idx & 7) << 2;
                int ok = (n0 + n) < N;
                const float* p = ok ? (B + (long)(n0 + n) * K + k0 + kc) : B;
                cpa16(sB + (n * 36 + kc) * 4, p, ok);
            }
        }
        cpa_commit();
    };

    auto compute = [&](int s) {
        const float* As = smbuf + s * 9216;
        const float* Bs = As + 4608;
#pragma unroll
        for (int kk = 0; kk < 32; kk += 8) {
            const int kA = kk + tg, kB = kA + 4;
            uint32_t bfr[4][2];
#pragma unroll
            for (int ns = 0; ns < 4; ns++) {
                int n = wnB + ns * 8 + g;
                bfr[ns][0] = __float_as_uint(TB == 0 ? Bs[kA * 136 + n] : Bs[n * 36 + kA]);
                bfr[ns][1] = __float_as_uint(TB == 0 ? Bs[kB * 136 + n] : Bs[n * 36 + kB]);
            }
#pragma unroll
            for (int ms = 0; ms < 4; ms++) {
                int m = wmB + ms * 16 + g;
                uint32_t a0 = __float_as_uint(TA == 0 ? As[m * 36 + kA] : As[kA * 136 + m]);
                uint32_t a1 = __float_as_uint(TA == 0 ? As[(m + 8) * 36 + kA] : As[kA * 136 + m + 8]);
                uint32_t a2 = __float_as_uint(TA == 0 ? As[m * 36 + kB] : As[kB * 136 + m]);
                uint32_t a3 = __float_as_uint(TA == 0 ? As[(m + 8) * 36 + kB] : As[kB * 136 + m + 8]);
#pragma unroll
                for (int ns = 0; ns < 4; ns++) {
                    asm volatile(
                        "mma.sync.aligned.m16n8k8.row.col.f32.tf32.tf32.f32 "
                        "{%0,%1,%2,%3}, {%4,%5,%6,%7}, {%8,%9}, {%0,%1,%2,%3};\n"
                        : "+f"(acc[ms][ns][0]), "+f"(acc[ms][ns][1]),
                          "+f"(acc[ms][ns][2]), "+f"(acc[ms][ns][3])
                        : "r"(a0), "r"(a1), "r"(a2), "r"(a3),
                          "r"(bfr[ns][0]), "r"(bfr[ns][1]));
                }
            }
        }
    };

    const int ktiles = K >> 5;
    issue_stage(0, 0);
    for (int kt = 0; kt < ktiles; kt++) {
        int buf = kt & 1;
        if (kt + 1 < ktiles) {
            issue_stage(kt + 1, buf ^ 1);
            asm volatile("cp.async.wait_group 1;\n");
        } else {
            asm volatile("cp.async.wait_group 0;\n");
        }
        __syncthreads();
        compute(buf);
        __syncthreads();
    }

    // epilogue
#pragma unroll
    for (int ms = 0; ms < 4; ms++) {
#pragma unroll
        for (int ns = 0; ns < 4; ns++) {
            int ncol = n0 + wnB + ns * 8 + tg * 2;
            if (ncol >= N) continue;
            int mrow = m0 + wmB + ms * 16 + g;
#pragma unroll
            for (int r = 0; r < 2; r++) {
                int m = mrow + r * 8;
                if (m >= M) continue;
                float v0 = acc[ms][ns][r * 2];
                float v1 = acc[ms][ns][r * 2 + 1];
                if (BIAS) { v0 += bias[ncol]; v1 += bias[ncol + 1]; }
                if (RELU) { v0 = fmaxf(v0, 0.f); v1 = fmaxf(v1, 0.f); }
                if (ROUND) { v0 = rna_tf32(v0); v1 = rna_tf32(v1); }
                float2* p = (float2*)(C + (long)m * N + ncol);
                if (ACCU) { float2 o = *p; v0 += o.x; v1 += o.y; }
                *p = make_float2(v0, v1);
            }
        }
    }
}

// ---------------- 7x7 local-window attention: scores in smem ----------------
__global__ __launch_bounds__(128) void attn_kernel(
    const float* __restrict__ Q, const float* __restrict__ K,
    const float* __restrict__ V, float* __restrict__ O)
{
    __shared__ float sc[128][49];
    const int b = blockIdx.z, nh = blockIdx.y;
    const int t = threadIdx.x;
    const int hw = blockIdx.x * 128 + t;
    if (hw >= HW) return;
    const int h = hw / W_IMG, w = hw % W_IMG;

    const int cbase = (b * C3 + nh * HD) * HW;
    const float* kb = K + cbase;
    const float* vb = V + cbase;

    float q[HD];
#pragma unroll
    for (int d = 0; d < HD; d++) q[d] = Q[cbase + d * HW + hw];

    // phase 1: all 49 scores + running max
    float mx = -1e30f;
    int o = 0;
    for (int i = 0; i < 7; i++) {
        int hh = min(max(h + i - 3, 0), H_IMG - 1);
#pragma unroll
        for (int j = 0; j < 7; j++) {
            int ww = min(max(w + j - 3, 0), W_IMG - 1);
            int off = hh * W_IMG + ww;
            float s = 0.f;
#pragma unroll
            for (int d = 0; d < HD; d++) s += q[d] * kb[d * HW + off];
            s *= ATT_SCALE;
            sc[t][o] = s;
            mx = fmaxf(mx, s);
            o++;
        }
    }

    // phase 2: exp + V-weighted accumulation
    float l = 0.f;
    float acc[HD];
#pragma unroll
    for (int d = 0; d < HD; d++) acc[d] = 0.f;
    o = 0;
    for (int i = 0; i < 7; i++) {
        int hh = min(max(h + i - 3, 0), H_IMG - 1);
#pragma unroll
        for (int j = 0; j < 7; j++) {
            int ww = min(max(w + j - 3, 0), W_IMG - 1);
            int off = hh * W_IMG + ww;
            float p = __expf(sc[t][o] - mx);
            l += p;
            o++;
#pragma unroll
            for (int d = 0; d < HD; d++) acc[d] += p * vb[d * HW + off];
        }
    }
    float inv = 1.f / l;
    float* ob = O + ((long)(b * HW + hw)) * C3 + nh * HD;   // NHWC
#pragma unroll
    for (int d = 0; d < HD; d += 4) {
        *(float4*)(ob + d) = make_float4(
            rna_tf32(acc[d] * inv),   rna_tf32(acc[d+1] * inv),
            rna_tf32(acc[d+2] * inv), rna_tf32(acc[d+3] * inv));
    }
}

// ---------------- warp-per-pixel LayerNorm (in place, NHWC, tf32-rounded out) ----
__global__ __launch_bounds__(256) void ln_kernel(
    float* __restrict__ X, const float* __restrict__ g, const float* __restrict__ bta,
    int npix)
{
    int wrp  = (blockIdx.x * blockDim.x + threadIdx.x) >> 5;
    int lane = threadIdx.x & 31;
    if (wrp >= npix) return;
    float* xp = X + (long)wrp * C3 + lane * 8;
    float4 v0 = *(float4*)xp;
    float4 v1 = *(float4*)(xp + 4);
    float s  = v0.x + v0.y + v0.z + v0.w + v1.x + v1.y + v1.z + v1.w;
    float ss = v0.x*v0.x + v0.y*v0.y + v0.z*v0.z + v0.w*v0.w
             + v1.x*v1.x + v1.y*v1.y + v1.z*v1.z + v1.w*v1.w;
#pragma unroll
    for (int o = 16; o; o >>= 1) {
        s  += __shfl_xor_sync(0xffffffffu, s,  o);
        ss += __shfl_xor_sync(0xffffffffu, ss, o);
    }
    float mu = s * (1.f / C3);
    float r  = rsqrtf(ss * (1.f / C3) - mu * mu + 1e-5f);
    const float* gp = g   + lane * 8;
    const float* bp = bta + lane * 8;
    float vv[8] = {v0.x, v0.y, v0.z, v0.w, v1.x, v1.y, v1.z, v1.w};
#pragma unroll
    for (int u = 0; u < 8; u++)
        vv[u] = rna_tf32((vv[u] - mu) * r * gp[u] + bp[u]);
    *(float4*)xp       = make_float4(vv[0], vv[1], vv[2], vv[3]);
    *(float4*)(xp + 4) = make_float4(vv[4], vv[5], vv[6], vv[7]);
}

// ---------------- x = LN2(x + y), NHWC -> NCHW output ----------------
__global__ __launch_bounds__(256) void final_kernel(
    const float* __restrict__ X, const float* __restrict__ Y,
    const float* __restrict__ g, const float* __restrict__ bta,
    float* __restrict__ out)
{
    __shared__ float sm[32][264];
    const int b  = blockIdx.y;
    const int p0 = blockIdx.x * 32;
    const int t = threadIdx.x, lane = t & 31, wid = t >> 5;

    for (int qq = 0; qq < 4; qq++) {
        int px = wid * 4 + qq;
        long base = ((long)b * HW + p0 + px) * C3 + lane * 8;
        float4 x0 = *(const float4*)(X + base);
        float4 x1 = *(const float4*)(X + base + 4);
        float4 y0 = *(const float4*)(Y + base);
        float4 y1 = *(const float4*)(Y + base + 4);
        float vv[8] = {x0.x + y0.x, x0.y + y0.y, x0.z + y0.z, x0.w + y0.w,
                       x1.x + y1.x, x1.y + y1.y, x1.z + y1.z, x1.w + y1.w};
        float s = 0.f, ss = 0.f;
#pragma unroll
        for (int u = 0; u < 8; u++) { s += vv[u]; ss += vv[u] * vv[u]; }
#pragma unroll
        for (int o = 16; o; o >>= 1) {
            s  += __shfl_xor_sync(0xffffffffu, s,  o);
            ss += __shfl_xor_sync(0xffffffffu, ss, o);
        }
        float mu = s * (1.f / C3);
        float r  = rsqrtf(ss * (1.f / C3) - mu * mu + 1e-5f);
#pragma unroll
        for (int u = 0; u < 8; u++) {
            int c = lane * 8 + u;
            sm[px][c] = (vv[u] - mu) * r * g[c] + bta[c];
        }
    }
    __syncthreads();
    int px = t & 31, c0 = t >> 5;
    for (int c = c0; c < C3; c += 8)
        out[((long)b * C3 + c) * HW + p0 + px] = sm[px][c];
}

// ---------------- launch ----------------
extern "C" void kernel_launch(void* const* d_in, const int* in_sizes, int n_in,
                              void* d_out, int out_size)
{
    const float* F_lidar = (const float*)d_in[0];
    const float* F_cam   = (const float*)d_in[1];
    const float* Wq  = (const float*)d_in[2];
    const float* Wk  = (const float*)d_in[3];
    const float* Wv  = (const float*)d_in[4];
    const float* Wo  = (const float*)d_in[5];
    const float* Wr  = (const float*)d_in[6];
    const float* g1  = (const float*)d_in[7];
    const float* b1  = (const float*)d_in[8];
    const float* g2  = (const float*)d_in[9];
    const float* b2  = (const float*)d_in[10];
    const float* W1  = (const float*)d_in[11];
    const float* bf1 = (const float*)d_in[12];
    const float* W2  = (const float*)d_in[13];
    const float* bf2 = (const float*)d_in[14];
    float* out = (float*)d_out;

    float *Q, *K, *V, *AO, *X, *Y, *Hd, *Fl, *Fc, *Wb;
    cudaGetSymbolAddress((void**)&Q,  g_Q);
    cudaGetSymbolAddress((void**)&K,  g_K);
    cudaGetSymbolAddress((void**)&V,  g_V);
    cudaGetSymbolAddress((void**)&AO, g_AO);
    cudaGetSymbolAddress((void**)&X,  g_X);
    cudaGetSymbolAddress((void**)&Y,  g_Y);
    cudaGetSymbolAddress((void**)&Hd, g_Hid);
    cudaGetSymbolAddress((void**)&Fl, g_Fl);
    cudaGetSymbolAddress((void**)&Fc, g_Fc);
    cudaGetSymbolAddress((void**)&Wb, g_Wb);

    // rounded-weight layout in g_Wb
    float* wq = Wb;            // 16384
    float* wk = Wb + 16384;    // 65536
    float* wv = Wb + 81920;    // 65536
    float* wo = Wb + 147456;   // 65536
    float* wr = Wb + 212992;   // 16384
    float* w1 = Wb + 229376;   // 262144
    float* w2 = Wb + 491520;   // 262144

    const int SMEM = 73728;
    cudaFuncSetAttribute(gemm_tc<0,0,0,0,0,0>, cudaFuncAttributeMaxDynamicSharedMemorySize, SMEM);
    cudaFuncSetAttribute(gemm_tc<0,1,0,0,0,0>, cudaFuncAttributeMaxDynamicSharedMemorySize, SMEM);
    cudaFuncSetAttribute(gemm_tc<1,1,1,0,0,0>, cudaFuncAttributeMaxDynamicSharedMemorySize, SMEM);
    cudaFuncSetAttribute(gemm_tc<0,0,0,1,1,1>, cudaFuncAttributeMaxDynamicSharedMemorySize, SMEM);
    cudaFuncSetAttribute(gemm_tc<0,0,0,0,1,0>, cudaFuncAttributeMaxDynamicSharedMemorySize, SMEM);

    dim3 blk(256);
    const long chw  = (long)C3 * HW;
    const long c1hw = (long)C1 * HW;
    const long xstr = (long)HW * C3;

    // ---- tf32-round all GEMM inputs ----
    auto rnd = [&](const float* s, float* d, int n) {
        int n4 = n >> 2;
        round_k<<<(n4 + 255) / 256, blk>>>((const float4*)s, (float4*)d, n4);
    };
    rnd(Wq, wq, C3 * C1);
    rnd(Wk, wk, C3 * C3);
    rnd(Wv, wv, C3 * C3);
    rnd(Wo, wo, C3 * C3);
    rnd(Wr, wr, C3 * C1);
    rnd(W1, w1, C3 * CF);
    rnd(W2, w2, CF * C3);
    rnd(F_lidar, Fl, BSZ * C1 * HW);
    rnd(F_cam,   Fc, BSZ * C3 * HW);

    // ---- projections (NCHW out) ----
    gemm_tc<0,0,0,0,0,0><<<dim3(313, 2, BSZ), blk, SMEM>>>(
        wq, Fl, nullptr, Q, C3, HW, C1, 0, c1hw, chw);
    gemm_tc<0,0,0,0,0,0><<<dim3(313, 2, BSZ), blk, SMEM>>>(
        wk, Fc, nullptr, K, C3, HW, C3, 0, chw, chw);
    gemm_tc<0,0,0,0,0,0><<<dim3(313, 2, BSZ), blk, SMEM>>>(
        wv, Fc, nullptr, V, C3, HW, C3, 0, chw, chw);

    // ---- attention (NHWC, tf32-rounded out) ----
    attn_kernel<<<dim3((HW + 127) / 128, NHEADS, BSZ), dim3(128)>>>(Q, K, V, AO);

    // ---- X = AO @ Wo^T ; X += F_lidar^T @ Wr^T ----
    gemm_tc<0,1,0,0,0,0><<<dim3(2, 625, 1), blk, SMEM>>>(
        AO, wo, nullptr, X, BSZ * HW, C3, C3, 0, 0, 0);
    gemm_tc<1,1,1,0,0,0><<<dim3(2, 313, BSZ), blk, SMEM>>>(
        Fl, wr, nullptr, X, HW, C3, C1, c1hw, 0, xstr);

    // ---- LN1 (in place, rounds X to tf32) ----
    ln_kernel<<<(BSZ * HW * 32 + 255) / 256, blk>>>(X, g1, b1, BSZ * HW);

    // ---- FFN ----
    gemm_tc<0,0,0,1,1,1><<<dim3(8, 625, 1), blk, SMEM>>>(
        X,  w1, bf1, Hd, BSZ * HW, CF, C3, 0, 0, 0);
    gemm_tc<0,0,0,0,1,0><<<dim3(2, 625, 1), blk, SMEM>>>(
        Hd, w2, bf2, Y,  BSZ * HW, C3, CF, 0, 0, 0);

    // ---- LN2(x+y) -> NCHW ----
    final_kernel<<<dim3(HW / 32, BSZ), blk>>>(X, Y, g2, b2, out);
}

// round 6
// speedup vs baseline: 1.2557x; 1.2557x over previous
#include <cuda_runtime.h>
#include <math.h>
#include <stdint.h>

#define H_IMG 200
#define W_IMG 200
#define HW    40000
#define C1    64
#define C3    256
#define NHEADS 8
#define HD    32
#define BSZ   2
#define CF    1024
#define ATT_SCALE 0.17677669529663687f   // 32^-0.5

// ---------------- static scratch ----------------
__device__ float g_Q  [BSZ * C3 * HW];   // NCHW
__device__ float g_K  [BSZ * C3 * HW];
__device__ float g_V  [BSZ * C3 * HW];
__device__ float g_AO [BSZ * HW * C3];   // NHWC
__device__ float g_X  [BSZ * HW * C3];   // NHWC
__device__ float g_Y  [BSZ * HW * C3];   // NHWC
__device__ float g_Hid[BSZ * HW * CF];

__device__ __forceinline__ float f2tf(float x) {
    uint32_t u;
    asm("cvt.rna.tf32.f32 %0, %1;" : "=r"(u) : "f"(x));
    return __uint_as_float(u);
}

// A smem: interleaved [tg][m][j]  (j = k/4, tg = k%4), plane stride 520 floats.
// One LDS.128 at (tg, m) -> k = {tg, tg+4, tg+8, tg+12}: A-frags for both kk steps.
// B smem: flat [k][136 + n].
#define ATG 520
#define ABUF 2080            // 4 * 520
#define BBUF 2176            // 16 * 136
#define SBUF (ABUF + BBUF)   // per stage

// ---------------- tf32 tensor-core GEMM, BK=16, 2-stage, reg-staged ----------------
// TA=0: A row-major [M,K] (M multiple of 128). TA=1: A stored [K,M].
// TB=0: B row-major [K,N]. TB=1: B stored [N,K] (B^T used).
template<int TA, int TB, int ACCU, int RELU, int BIAS>
__global__ __launch_bounds__(256) void gemm_tc(
    const float* __restrict__ A, const float* __restrict__ B,
    const float* __restrict__ bias, float* __restrict__ C,
    int M, int N, int K, long aStr, long bStr, long cStr)
{
    __shared__ float sm[2 * SBUF];
    A += (long)blockIdx.z * aStr;
    B += (long)blockIdx.z * bStr;
    C += (long)blockIdx.z * cStr;

    const int m0 = blockIdx.y * 128;
    const int n0 = blockIdx.x * 128;
    const int t    = threadIdx.x;
    const int lane = t & 31, w = t >> 5;
    const int g  = lane >> 2, tg = lane & 3;
    const int wmB = (w & 1) * 64, wnB = (w >> 1) * 32;

    float acc[4][4][4];
#pragma unroll
    for (int i = 0; i < 4; i++)
#pragma unroll
        for (int j = 0; j < 4; j++)
#pragma unroll
            for (int r = 0; r < 4; r++) acc[i][j][r] = 0.f;

    float ra[2][4], rb[2][4];

    auto loadA = [&](int k0) {
#pragma unroll
        for (int v = 0; v < 2; v++) {
            int f = t + v * 256;
            if (TA == 0) {
                int m = f >> 2, kc = (f & 3) << 2;
                float4 q = *(const float4*)(A + (long)(m0 + m) * K + k0 + kc);
                ra[v][0] = q.x; ra[v][1] = q.y; ra[v][2] = q.z; ra[v][3] = q.w;
            } else {
                int k4 = f >> 7, m = f & 127;
                bool ok = (m0 + m) < M;
                const float* p = A + (long)(k0 + 4 * k4) * M + (ok ? m0 + m : 0);
#pragma unroll
                for (int i = 0; i < 4; i++)
                    ra[v][i] = ok ? p[(long)i * M] : 0.f;
            }
        }
    };
    auto loadB = [&](int k0) {
#pragma unroll
        for (int v = 0; v < 2; v++) {
            int f = t + v * 256;
            if (TB == 0) {
                int k = f >> 5, n = (f & 31) << 2;
                float4 q = make_float4(0.f, 0.f, 0.f, 0.f);
                if (n0 + n < N)
                    q = *(const float4*)(B + (long)(k0 + k) * N + n0 + n);
                rb[v][0] = q.x; rb[v][1] = q.y; rb[v][2] = q.z; rb[v][3] = q.w;
            } else {
                int n = f >> 2, kc = (f & 3) << 2;
                float4 q = make_float4(0.f, 0.f, 0.f, 0.f);
                if (n0 + n < N)
                    q = *(const float4*)(B + (long)(n0 + n) * K + k0 + kc);
                rb[v][0] = q.x; rb[v][1] = q.y; rb[v][2] = q.z; rb[v][3] = q.w;
            }
        }
    };
    auto storeAB = [&](int s) {
        float* As = sm + s * SBUF;
        float* Bs = As + ABUF;
#pragma unroll
        for (int v = 0; v < 2; v++) {
            int f = t + v * 256;
            if (TA == 0) {
                int m = f >> 2, j = f & 3;
#pragma unroll
                for (int i = 0; i < 4; i++)          // k = j*4 + i -> plane i? no: k%4 cycles with i
                    As[ATG * i + 4 * m + j] = f2tf(ra[v][i]);
            } else {
                int k4 = f >> 7, m = f & 127;
#pragma unroll
                for (int i = 0; i < 4; i++)          // k = 4*k4 + i -> tg=i, j=k4
                    As[ATG * i + 4 * m + k4] = f2tf(ra[v][i]);
            }
            if (TB == 0) {
                int k = f >> 5, n = (f & 31) << 2;
                float4 q = make_float4(f2tf(rb[v][0]), f2tf(rb[v][1]),
                                       f2tf(rb[v][2]), f2tf(rb[v][3]));
                *(float4*)&Bs[k * 136 + n] = q;
            } else {
                int n = f >> 2, kc = (f & 3) << 2;
#pragma unroll
                for (int i = 0; i < 4; i++)
                    Bs[(kc + i) * 136 + n] = f2tf(rb[v][i]);
            }
        }
    };
    auto compute = [&](int s) {
        const float* As = sm + s * SBUF;
        const float* Bs = As + ABUF;
        // B fragments for both kk steps (kk=0: rows tg,tg+4; kk=8: rows tg+8,tg+12)
        uint32_t bfr[2][4][2];
#pragma unroll
        for (int kk2 = 0; kk2 < 2; kk2++) {
            int rA = kk2 * 8 + tg, rB = rA + 4;
#pragma unroll
            for (int ns = 0; ns < 4; ns++) {
                int n = wnB + ns * 8 + g;
                bfr[kk2][ns][0] = __float_as_uint(Bs[rA * 136 + n]);
                bfr[kk2][ns][1] = __float_as_uint(Bs[rB * 136 + n]);
            }
        }
#pragma unroll
        for (int ms = 0; ms < 4; ms++) {
            int m = wmB + ms * 16 + g;
            float4 alo = *(const float4*)&As[ATG * tg + 4 * m];
            float4 ahi = *(const float4*)&As[ATG * tg + 4 * (m + 8)];
#pragma unroll
            for (int ns = 0; ns < 4; ns++) {
                asm volatile(
                    "mma.sync.aligned.m16n8k8.row.col.f32.tf32.tf32.f32 "
                    "{%0,%1,%2,%3}, {%4,%5,%6,%7}, {%8,%9}, {%0,%1,%2,%3};\n"
                    : "+f"(acc[ms][ns][0]), "+f"(acc[ms][ns][1]),
                      "+f"(acc[ms][ns][2]), "+f"(acc[ms][ns][3])
                    : "r"(__float_as_uint(alo.x)), "r"(__float_as_uint(ahi.x)),
                      "r"(__float_as_uint(alo.y)), "r"(__float_as_uint(ahi.y)),
                      "r"(bfr[0][ns][0]), "r"(bfr[0][ns][1]));
                asm volatile(
                    "mma.sync.aligned.m16n8k8.row.col.f32.tf32.tf32.f32 "
                    "{%0,%1,%2,%3}, {%4,%5,%6,%7}, {%8,%9}, {%0,%1,%2,%3};\n"
                    : "+f"(acc[ms][ns][0]), "+f"(acc[ms][ns][1]),
                      "+f"(acc[ms][ns][2]), "+f"(acc[ms][ns][3])
                    : "r"(__float_as_uint(alo.z)), "r"(__float_as_uint(ahi.z)),
                      "r"(__float_as_uint(alo.w)), "r"(__float_as_uint(ahi.w)),
                      "r"(bfr[1][ns][0]), "r"(bfr[1][ns][1]));
            }
        }
    };

    const int ktiles = K >> 4;
    loadA(0); loadB(0);
    storeAB(0);
    __syncthreads();
    for (int kt = 0; kt < ktiles; kt++) {
        int buf = kt & 1;
        if (kt + 1 < ktiles) { loadA((kt + 1) << 4); loadB((kt + 1) << 4); }
        compute(buf);
        if (kt + 1 < ktiles) storeAB(buf ^ 1);
        __syncthreads();
    }

    // epilogue
#pragma unroll
    for (int ms = 0; ms < 4; ms++) {
#pragma unroll
        for (int ns = 0; ns < 4; ns++) {
            int ncol = n0 + wnB + ns * 8 + tg * 2;
            if (ncol >= N) continue;
            int mrow = m0 + wmB + ms * 16 + g;
#pragma unroll
            for (int r = 0; r < 2; r++) {
                int m = mrow + r * 8;
                if (m >= M) continue;
                float v0 = acc[ms][ns][r * 2];
                float v1 = acc[ms][ns][r * 2 + 1];
                if (BIAS) { v0 += bias[ncol]; v1 += bias[ncol + 1]; }
                if (RELU) { v0 = fmaxf(v0, 0.f); v1 = fmaxf(v1, 0.f); }
                float2* p = (float2*)(C + (long)m * N + ncol);
                if (ACCU) { float2 o = *p; v0 += o.x; v1 += o.y; }
                *p = make_float2(v0, v1);
            }
        }
    }
}

// ---------------- 7x7 local-window attention (NCHW in, NHWC out) ----------------
__global__ __launch_bounds__(256) void attn_kernel(
    const float* __restrict__ Q, const float* __restrict__ K,
    const float* __restrict__ V, float* __restrict__ O)
{
    const int b = blockIdx.z, nh = blockIdx.y;
    const int hw = blockIdx.x * blockDim.x + threadIdx.x;
    if (hw >= HW) return;
    const int h = hw / W_IMG, w = hw % W_IMG;

    const int cbase = (b * C3 + nh * HD) * HW;
    const float* qb = Q + cbase + hw;
    const float* kb = K + cbase;
    const float* vb = V + cbase;

    float q[HD];
#pragma unroll
    for (int d = 0; d < HD; d++) q[d] = qb[d * HW];

    float m = -1e30f, l = 0.f;
    float acc[HD];
#pragma unroll
    for (int d = 0; d < HD; d++) acc[d] = 0.f;

    for (int i = 0; i < 7; i++) {
        int hh = min(max(h + i - 3, 0), H_IMG - 1);
        for (int j = 0; j < 7; j++) {
            int ww = min(max(w + j - 3, 0), W_IMG - 1);
            int off = hh * W_IMG + ww;
            float s = 0.f;
#pragma unroll
            for (int d = 0; d < HD; d++) s += q[d] * kb[d * HW + off];
            s *= ATT_SCALE;
            float mn = fmaxf(m, s);
            float corr = __expf(m - mn);
            float p    = __expf(s - mn);
            l = l * corr + p;
#pragma unroll
            for (int d = 0; d < HD; d++)
                acc[d] = acc[d] * corr + p * vb[d * HW + off];
            m = mn;
        }
    }
    float inv = 1.f / l;
    float* ob = O + ((long)(b * HW + hw)) * C3 + nh * HD;   // NHWC
#pragma unroll
    for (int d = 0; d < HD; d += 4) {
        *(float4*)(ob + d) = make_float4(acc[d] * inv, acc[d+1] * inv,
                                         acc[d+2] * inv, acc[d+3] * inv);
    }
}

// ---------------- warp-per-pixel LayerNorm (in place, NHWC) --------
__global__ __launch_bounds__(256) void ln_kernel(
    float* __restrict__ X, const float* __restrict__ g, const float* __restrict__ bta,
    int npix)
{
    int wrp  = (blockIdx.x * blockDim.x + threadIdx.x) >> 5;
    int lane = threadIdx.x & 31;
    if (wrp >= npix) return;
    float* xp = X + (long)wrp * C3 + lane * 8;
    float4 v0 = *(float4*)xp;
    float4 v1 = *(float4*)(xp + 4);
    float s  = v0.x + v0.y + v0.z + v0.w + v1.x + v1.y + v1.z + v1.w;
    float ss = v0.x*v0.x + v0.y*v0.y + v0.z*v0.z + v0.w*v0.w
             + v1.x*v1.x + v1.y*v1.y + v1.z*v1.z + v1.w*v1.w;
#pragma unroll
    for (int o = 16; o; o >>= 1) {
        s  += __shfl_xor_sync(0xffffffffu, s,  o);
        ss += __shfl_xor_sync(0xffffffffu, ss, o);
    }
    float mu = s * (1.f / C3);
    float r  = rsqrtf(ss * (1.f / C3) - mu * mu + 1e-5f);
    const float* gp = g   + lane * 8;
    const float* bp = bta + lane * 8;
    float vv[8] = {v0.x, v0.y, v0.z, v0.w, v1.x, v1.y, v1.z, v1.w};
#pragma unroll
    for (int u = 0; u < 8; u++) vv[u] = (vv[u] - mu) * r * gp[u] + bp[u];
    *(float4*)xp       = make_float4(vv[0], vv[1], vv[2], vv[3]);
    *(float4*)(xp + 4) = make_float4(vv[4], vv[5], vv[6], vv[7]);
}

// ---------------- x = LN2(x + y), NHWC -> NCHW output ----------------
__global__ __launch_bounds__(256) void final_kernel(
    const float* __restrict__ X, const float* __restrict__ Y,
    const float* __restrict__ g, const float* __restrict__ bta,
    float* __restrict__ out)
{
    __shared__ float sm[32][264];
    const int b  = blockIdx.y;
    const int p0 = blockIdx.x * 32;
    const int t = threadIdx.x, lane = t & 31, wid = t >> 5;

    for (int qq = 0; qq < 4; qq++) {
        int px = wid * 4 + qq;
        long base = ((long)b * HW + p0 + px) * C3 + lane * 8;
        float4 x0 = *(const float4*)(X + base);
        float4 x1 = *(const float4*)(X + base + 4);
        float4 y0 = *(const float4*)(Y + base);
        float4 y1 = *(const float4*)(Y + base + 4);
        float vv[8] = {x0.x + y0.x, x0.y + y0.y, x0.z + y0.z, x0.w + y0.w,
                       x1.x + y1.x, x1.y + y1.y, x1.z + y1.z, x1.w + y1.w};
        float s = 0.f, ss = 0.f;
#pragma unroll
        for (int u = 0; u < 8; u++) { s += vv[u]; ss += vv[u] * vv[u]; }
#pragma unroll
        for (int o = 16; o; o >>= 1) {
            s  += __shfl_xor_sync(0xffffffffu, s,  o);
            ss += __shfl_xor_sync(0xffffffffu, ss, o);
        }
        float mu = s * (1.f / C3);
        float r  = rsqrtf(ss * (1.f / C3) - mu * mu + 1e-5f);
#pragma unroll
        for (int u = 0; u < 8; u++) {
            int c = lane * 8 + u;
            sm[px][c] = (vv[u] - mu) * r * g[c] + bta[c];
        }
    }
    __syncthreads();
    int px = t & 31, c0 = t >> 5;
    for (int c = c0; c < C3; c += 8)
        out[((long)b * C3 + c) * HW + p0 + px] = sm[px][c];
}

// ---------------- launch ----------------
extern "C" void kernel_launch(void* const* d_in, const int* in_sizes, int n_in,
                              void* d_out, int out_size)
{
    const float* F_lidar = (const float*)d_in[0];
    const float* F_cam   = (const float*)d_in[1];
    const float* Wq  = (const float*)d_in[2];
    const float* Wk  = (const float*)d_in[3];
    const float* Wv  = (const float*)d_in[4];
    const float* Wo  = (const float*)d_in[5];
    const float* Wr  = (const float*)d_in[6];
    const float* g1  = (const float*)d_in[7];
    const float* b1  = (const float*)d_in[8];
    const float* g2  = (const float*)d_in[9];
    const float* b2  = (const float*)d_in[10];
    const float* W1  = (const float*)d_in[11];
    const float* bf1 = (const float*)d_in[12];
    const float* W2  = (const float*)d_in[13];
    const float* bf2 = (const float*)d_in[14];
    float* out = (float*)d_out;

    float *Q, *K, *V, *AO, *X, *Y, *Hd;
    cudaGetSymbolAddress((void**)&Q,  g_Q);
    cudaGetSymbolAddress((void**)&K,  g_K);
    cudaGetSymbolAddress((void**)&V,  g_V);
    cudaGetSymbolAddress((void**)&AO, g_AO);
    cudaGetSymbolAddress((void**)&X,  g_X);
    cudaGetSymbolAddress((void**)&Y,  g_Y);
    cudaGetSymbolAddress((void**)&Hd, g_Hid);

    dim3 blk(256);
    const long chw  = (long)C3 * HW;
    const long c1hw = (long)C1 * HW;
    const long xstr = (long)HW * C3;

    // projections (NCHW out)
    gemm_tc<0,0,0,0,0><<<dim3(313, 2, BSZ), blk>>>(
        Wq, F_lidar, nullptr, Q, C3, HW, C1, 0, c1hw, chw);
    gemm_tc<0,0,0,0,0><<<dim3(313, 2, BSZ), blk>>>(
        Wk, F_cam, nullptr, K, C3, HW, C3, 0, chw, chw);
    gemm_tc<0,0,0,0,0><<<dim3(313, 2, BSZ), blk>>>(
        Wv, F_cam, nullptr, V, C3, HW, C3, 0, chw, chw);

    // attention (NHWC out)
    attn_kernel<<<dim3((HW + 255) / 256, NHEADS, BSZ), blk>>>(Q, K, V, AO);

    // X = AO @ Wo^T ; X += F_lidar^T @ Wr^T
    gemm_tc<0,1,0,0,0><<<dim3(2, 625, 1), blk>>>(
        AO, Wo, nullptr, X, BSZ * HW, C3, C3, 0, 0, 0);
    gemm_tc<1,1,1,0,0><<<dim3(2, 313, BSZ), blk>>>(
        F_lidar, Wr, nullptr, X, HW, C3, C1, c1hw, 0, xstr);

    // LN1 in place
    ln_kernel<<<(BSZ * HW * 32 + 255) / 256, blk>>>(X, g1, b1, BSZ * HW);

    // FFN
    gemm_tc<0,0,0,1,1><<<dim3(8, 625, 1), blk>>>(
        X,  W1, bf1, Hd, BSZ * HW, CF, C3, 0, 0, 0);
    gemm_tc<0,0,0,0,1><<<dim3(2, 625, 1), blk>>>(
        Hd, W2, bf2, Y,  BSZ * HW, C3, CF, 0, 0, 0);

    // LN2(x+y) -> NCHW
    final_kernel<<<dim3(HW / 32, BSZ), blk>>>(X, Y, g2, b2, out);
}